// round 12
// baseline (speedup 1.0000x reference)
#include <cuda_runtime.h>
#include <math.h>

#define BC     4
#define NODES  4096
#define FEAT   64
#define OUTD   32
#define NEDGES (32 * NODES)
#define NW     (NODES / 32)   // 128 bitmap words per row
#define CAPW   128            // neighbor capacity (deg ~ Poisson(32))

// Scratch (no allocations in kernel_launch). g_bits is zero at module load;
// k_gat re-zeroes every word it consumes, so the bitmap is always clear when
// k_z_set's atomicOr scatter runs on the next call/replay.
// z stored batch-PAIR interleaved: g_z2[pair][node][feat] = (z_{2p}, z_{2p+1})
__device__ float2   g_z2[2 * NODES * OUTD];   // 2 MB
__device__ unsigned g_bits[NODES * NW];       // 2 MB

// ---------------------------------------------------------------------------
// Fused: z = h @ W (2 rows/warp; h warp-uniform float4, W staged in smem) +
// edge scatter. Writes into the pair-interleaved layout.
__global__ __launch_bounds__(256) void k_z_set(const float* __restrict__ h,
                                               const float* __restrict__ W,
                                               const int* __restrict__ erow,
                                               const int* __restrict__ ecol) {
    __shared__ __align__(16) float Ws[FEAT * OUTD];       // 8 KB
    const int tid = threadIdx.x;
    ((float4*)Ws)[tid]       = ((const float4*)W)[tid];
    ((float4*)Ws)[tid + 256] = ((const float4*)W)[tid + 256];

    const int gid = blockIdx.x * 256 + tid;
    if (gid < NEDGES) {
        const int r = erow[gid], c = ecol[gid];
        atomicOr(&g_bits[r * NW + (c >> 5)], 1u << (c & 31));
    }
    __syncthreads();

    const int lane = tid & 31, wid = tid >> 5;
    const int r0 = (blockIdx.x * 8 + wid) * 2;     // global row in [0, BC*NODES)
    const int b  = r0 / NODES;                     // r0,r0+1 share batch
    const int n  = r0 - b * NODES;
    const int pair = b >> 1, comp = b & 1;
    const float4* h4 = (const float4*)(h + (long)r0 * FEAT);
    float a0 = 0.f, a1 = 0.f;
#pragma unroll
    for (int q = 0; q < 16; q++) {
        const float4 h0 = h4[q];
        const float4 h1 = h4[16 + q];
        const float w0 = Ws[(4 * q + 0) * OUTD + lane];
        const float w1 = Ws[(4 * q + 1) * OUTD + lane];
        const float w2 = Ws[(4 * q + 2) * OUTD + lane];
        const float w3 = Ws[(4 * q + 3) * OUTD + lane];
        a0 = fmaf(h0.x, w0, a0); a0 = fmaf(h0.y, w1, a0);
        a0 = fmaf(h0.z, w2, a0); a0 = fmaf(h0.w, w3, a0);
        a1 = fmaf(h1.x, w0, a1); a1 = fmaf(h1.y, w1, a1);
        a1 = fmaf(h1.z, w2, a1); a1 = fmaf(h1.w, w3, a1);
    }
    float* gz = (float*)g_z2;
    gz[(((long)pair * NODES + n)     * OUTD + lane) * 2 + comp] = a0;
    gz[(((long)pair * NODES + n + 1) * OUTD + lane) * 2 + comp] = a1;
}

// ---------------------------------------------------------------------------
// Order-preserving float<->uint transform for __reduce_max_sync.
__device__ __forceinline__ unsigned f2ord(float f) {
    unsigned u = __float_as_uint(f);
    return (u & 0x80000000u) ? ~u : (u | 0x80000000u);
}
__device__ __forceinline__ float ord2f(unsigned u) {
    return __uint_as_float((u & 0x80000000u) ? (u & 0x7fffffffu) : ~u);
}

// One 128-thread block per TWO rows; warp w -> (row 2*bid + (w>>1), pair w&1).
// Phase A built ONCE per row (pair-0 warp); pair-1 warp zeroes the bitmap.
// Tile row: 32 float2 (= 16 f4), padded to 17 f4 for conflict-freedom.
#define TROWS 16
#define RF4   17                               // f4 stride per tile row
__global__ __launch_bounds__(128, 10) void k_gat(float* __restrict__ out) {
    __shared__ unsigned short nbr[2][CAPW];
    __shared__ int s_M[2];
    __shared__ __align__(16) float  tile[4][TROWS * RF4 * 4];
    __shared__ __align__(16) float2 s_zi[4][OUTD];
    __shared__ __align__(16) float2 s_e[4][TROWS];

    const int tid  = threadIdx.x;
    const int lane = tid & 31, wid = tid >> 5;
    const int rl   = wid >> 1;                 // row slot 0/1 in block
    const int pair = wid & 1;                  // batch pair 0/1
    const int row  = 2 * blockIdx.x + rl;

    const float2* zb2 = g_z2 + (long)pair * NODES * OUTD;
    const float4* zb4 = (const float4*)zb2;    // 16 f4 per node row

    // prefetch z_i for this (row, pair)
    s_zi[wid][lane] = zb2[row * OUTD + lane];

    // --- Phase A: pair-0 warps read bitmap + build; pair-1 warps zero it ---
    uint4 wv;
    if (pair == 0)
        wv = ((const uint4*)(g_bits + row * NW))[lane];
    __syncthreads();
    if (pair == 1)                             // leave bitmap clean for next run
        ((uint4*)(g_bits + row * NW))[lane] = make_uint4(0u, 0u, 0u, 0u);
    if (pair == 0) {
        const int cnt = __popc(wv.x) + __popc(wv.y) + __popc(wv.z) + __popc(wv.w);
        int v = cnt;
#pragma unroll
        for (int o = 1; o < 32; o <<= 1) {
            int t = __shfl_up_sync(0xffffffffu, v, o);
            if (lane >= o) v += t;
        }
        int M = __shfl_sync(0xffffffffu, v, 31);
        int off = v - cnt;
        const int cb = lane * 128;
        unsigned wsx[4] = {wv.x, wv.y, wv.z, wv.w};
#pragma unroll
        for (int q = 0; q < 4; q++) {
            unsigned ww = wsx[q];
            while (ww) {
                int b = __ffs(ww) - 1;
                if (off < CAPW) nbr[rl][off] = (unsigned short)(cb + q * 32 + b);
                off++;
                ww &= ww - 1;
            }
        }
        if (lane == 0) s_M[rl] = (M > CAPW) ? CAPW : M;
    }
    __syncthreads();
    const int M = s_M[rl];

    // --- Phase B: warp = (row rl, batches 2*pair, 2*pair+1) ---
    float4*       tw4  = (float4*)tile[wid];
    const float2* twl2 = ((const float2*)tile[wid]) + lane;   // feature = lane
    const float4* z4   = (const float4*)s_zi[wid];            // 16 f4
    const float4* se4  = (const float4*)s_e[wid];             // 8 f4
    const int kn   = lane >> 1;                // neighbor slot 0..15
    const int half = lane & 1;                 // feature half of the dot

    float m0 = -INFINITY, m1 = -INFINITY, ss0 = 0.f, ss1 = 0.f;
    float2 accA = make_float2(0.f, 0.f), accB = make_float2(0.f, 0.f);

    for (int t = 0; t < M; t += TROWS) {
        const int  rem = (M - t < TROWS) ? (M - t) : TROWS;   // warp-uniform
        const bool inr = (kn < rem);
        const int  j   = nbr[rl][t + (inr ? kn : 0)];         // clamped

        // stage 16 node rows x 16 f4 (256B each, BOTH batches) = 8 f4/lane
#pragma unroll
        for (int i = 0; i < 8; i++) {
            const int e  = i * 32 + lane;
            const int k  = e >> 4, d4 = e & 15;
            const int jk = __shfl_sync(0xffffffffu, j, 2 * k);
            tw4[k * RF4 + d4] = zb4[jk * 16 + d4];
        }
        __syncwarp();

        // half-dot for BOTH batches: features [16*half, 16*half+16)
        float p0a = 0.f, p0b = 0.f, p1a = 0.f, p1b = 0.f;
#pragma unroll
        for (int i = 0; i < 8; i++) {
            const float4 vv = tw4[kn * RF4 + half * 8 + i];   // (f:b0,b1 f+1:b0,b1)
            const float4 zz = z4[half * 8 + i];
            p0a = fmaf(vv.x, zz.x, p0a);
            p1a = fmaf(vv.y, zz.y, p1a);
            p0b = fmaf(vv.z, zz.z, p0b);
            p1b = fmaf(vv.w, zz.w, p1b);
        }
        float p0 = p0a + p0b, p1 = p1a + p1b;
        p0 += __shfl_xor_sync(0xffffffffu, p0, 1);
        p1 += __shfl_xor_sync(0xffffffffu, p1, 1);
        const float s0 = (p0 >= 0.f) ? p0 : 0.1f * p0;        // LeakyReLU(0.1)
        const float s1 = (p1 >= 0.f) ? p1 : 0.1f * p1;
        const bool  v0 = inr && (s0 != 0.f);                  // att==0 -> masked
        const bool  v1 = inr && (s1 != 0.f);
        const float sv0 = v0 ? s0 : -INFINITY;
        const float sv1 = v1 ? s1 : -INFINITY;

        const float tm0 = ord2f(__reduce_max_sync(0xffffffffu, f2ord(sv0)));
        const float tm1 = ord2f(__reduce_max_sync(0xffffffffu, f2ord(sv1)));
        const float nm0 = fmaxf(m0, tm0), nm1 = fmaxf(m1, tm1);
        const float ns0 = (nm0 > -INFINITY) ? nm0 : 0.f;      // NaN guard
        const float ns1 = (nm1 > -INFINITY) ? nm1 : 0.f;
        const float c0 = __expf(m0 - ns0);                    // 0 when m=-inf
        const float c1 = __expf(m1 - ns1);
        const float e0 = v0 ? __expf(sv0 - ns0) : 0.f;
        const float e1 = v1 ? __expf(sv1 - ns1) : 0.f;
        if (half == 0) s_e[wid][kn] = make_float2(e0, e1);
        m0 = nm0;  m1 = nm1;
        accA.x *= c0;  accB.x *= c0;  ss0 *= c0;
        accA.y *= c1;  accB.y *= c1;  ss1 *= c1;
        __syncwarp();

        // aggregation: 8 x (e-f4 bcast + 2 tile LDS.64 + 4 FMA), both batches
        float es0 = 0.f, es1 = 0.f;
#pragma unroll
        for (int k4 = 0; k4 < 8; k4++) {
            const float4 ev = se4[k4];                  // slots 2k4, 2k4+1
            const float2 t0v = twl2[(2 * k4)     * (RF4 * 2)];
            const float2 t1v = twl2[(2 * k4 + 1) * (RF4 * 2)];
            accA.x = fmaf(ev.x, t0v.x, accA.x);
            accA.y = fmaf(ev.y, t0v.y, accA.y);
            accB.x = fmaf(ev.z, t1v.x, accB.x);
            accB.y = fmaf(ev.w, t1v.y, accB.y);
            es0 += ev.x + ev.z;  es1 += ev.y + ev.w;
        }
        ss0 += es0;  ss1 += es1;
        __syncwarp();
    }

    float o0, o1;
    if (m0 > -INFINITY) {
        o0 = (accA.x + accB.x) / ss0;
    } else {                     // fully-masked row: uniform over ALL columns
        float s2 = 0.f;
        for (int n = 0; n < NODES; n++) s2 += zb2[n * OUTD + lane].x;
        o0 = s2 * (1.f / (float)NODES);
    }
    if (m1 > -INFINITY) {
        o1 = (accA.y + accB.y) / ss1;
    } else {
        float s2 = 0.f;
        for (int n = 0; n < NODES; n++) s2 += zb2[n * OUTD + lane].y;
        o1 = s2 * (1.f / (float)NODES);
    }
    out[((2 * pair)     * NODES + row) * OUTD + lane] = o0;
    out[((2 * pair + 1) * NODES + row) * OUTD + lane] = o1;
}

// ---------------------------------------------------------------------------
extern "C" void kernel_launch(void* const* d_in, const int* in_sizes, int n_in,
                              void* d_out, int out_size) {
    const float* h       = (const float*)d_in[0];
    const float* W       = (const float*)d_in[1];
    const int*   adj_row = (const int*)d_in[2];
    const int*   adj_col = (const int*)d_in[3];
    float*       out     = (float*)d_out;

    k_z_set<<<(BC * NODES) / 16, 256>>>(h, W, adj_row, adj_col);
    k_gat  <<<NODES / 2, 128>>>(out);
}

// round 13
// speedup vs baseline: 1.3611x; 1.3611x over previous
#include <cuda_runtime.h>
#include <math.h>

#define BC     4
#define NODES  4096
#define FEAT   64
#define OUTD   32
#define NEDGES (32 * NODES)
#define NW     (NODES / 32)   // 128 bitmap words per row
#define CAPW   128            // per-warp neighbor capacity (deg ~ Poisson(32))

// Scratch (no allocations in kernel_launch). g_bits is zero at module load;
// k_gat re-zeroes every word it consumes, so the bitmap is always clear when
// k_z_set's atomicOr scatter runs on the next call/replay.
__device__ float    g_z[BC * NODES * OUTD];   // 2 MB: z = h @ W
__device__ unsigned g_bits[NODES * NW];       // 2 MB: dedup'd adjacency bitmap

// ---------------------------------------------------------------------------
// Fused: z = h @ W (2 rows/warp; h warp-uniform float4, W staged in smem once
// per block) + edge scatter.
__global__ __launch_bounds__(256) void k_z_set(const float* __restrict__ h,
                                               const float* __restrict__ W,
                                               const int* __restrict__ erow,
                                               const int* __restrict__ ecol) {
    __shared__ __align__(16) float Ws[FEAT * OUTD];       // 8 KB
    const int tid = threadIdx.x;
    ((float4*)Ws)[tid]       = ((const float4*)W)[tid];
    ((float4*)Ws)[tid + 256] = ((const float4*)W)[tid + 256];

    const int gid = blockIdx.x * 256 + tid;
    if (gid < NEDGES) {
        const int r = erow[gid], c = ecol[gid];
        atomicOr(&g_bits[r * NW + (c >> 5)], 1u << (c & 31));
    }
    __syncthreads();

    const int lane = tid & 31, wid = tid >> 5;
    const int r0 = (blockIdx.x * 8 + wid) * 2;
    const float4* h4 = (const float4*)(h + (long)r0 * FEAT);
    float a0 = 0.f, a1 = 0.f;
#pragma unroll
    for (int q = 0; q < 16; q++) {
        const float4 h0 = h4[q];
        const float4 h1 = h4[16 + q];
        const float w0 = Ws[(4 * q + 0) * OUTD + lane];
        const float w1 = Ws[(4 * q + 1) * OUTD + lane];
        const float w2 = Ws[(4 * q + 2) * OUTD + lane];
        const float w3 = Ws[(4 * q + 3) * OUTD + lane];
        a0 = fmaf(h0.x, w0, a0); a0 = fmaf(h0.y, w1, a0);
        a0 = fmaf(h0.z, w2, a0); a0 = fmaf(h0.w, w3, a0);
        a1 = fmaf(h1.x, w0, a1); a1 = fmaf(h1.y, w1, a1);
        a1 = fmaf(h1.z, w2, a1); a1 = fmaf(h1.w, w3, a1);
    }
    g_z[(r0 + 0) * OUTD + lane] = a0;
    g_z[(r0 + 1) * OUTD + lane] = a1;
}

// ---------------------------------------------------------------------------
// Order-preserving float<->uint transform for __reduce_max_sync.
__device__ __forceinline__ unsigned f2ord(float f) {
    unsigned u = __float_as_uint(f);
    return (u & 0x80000000u) ? ~u : (u | 0x80000000u);
}
__device__ __forceinline__ float ord2f(unsigned u) {
    return __uint_as_float((u & 0x80000000u) ? (u & 0x7fffffffu) : ~u);
}

// One block per destination row; warp w owns batch w end-to-end.
// 16-row tiles; SOFTWARE-PIPELINED gather: next tile's 4 LDG.128 are issued
// into registers right after the current staging sync, hiding L2 latency
// behind the current tile's dot/softmax/aggregation. Single tile buffer.
#define TROWS 16
#define TPAD  36
__global__ __launch_bounds__(128, 9) void k_gat(float* __restrict__ out) {
    __shared__ unsigned short nbr[4][CAPW];
    __shared__ __align__(16) float tile[4][TROWS * TPAD];
    __shared__ __align__(16) float s_zi[4][32];
    __shared__ __align__(16) float s_e[4][TROWS];

    const int row  = blockIdx.x;
    const int tid  = threadIdx.x;
    const int lane = tid & 31, wid = tid >> 5;

    const float*  zb  = g_z + wid * NODES * OUTD;
    const float4* zb4 = (const float4*)zb;

    // two overlapping prefetches: z_i and this lane's 4 bitmap words
    const float zi = zb[row * OUTD + lane];
    const uint4 wv = ((const uint4*)(g_bits + row * NW))[lane];
    s_zi[wid][lane] = zi;

    // --- Phase A (per-warp): count, scan, extract ---
    const int cnt = __popc(wv.x) + __popc(wv.y) + __popc(wv.z) + __popc(wv.w);
    int v = cnt;
#pragma unroll
    for (int o = 1; o < 32; o <<= 1) {
        int t = __shfl_up_sync(0xffffffffu, v, o);
        if (lane >= o) v += t;
    }
    int M = __shfl_sync(0xffffffffu, v, 31);
    int off = v - cnt;
    const int cb = lane * 128;
    unsigned ws[4] = {wv.x, wv.y, wv.z, wv.w};
#pragma unroll
    for (int q = 0; q < 4; q++) {
        unsigned ww = ws[q];
        while (ww) {
            int b = __ffs(ww) - 1;
            if (off < CAPW) nbr[wid][off] = (unsigned short)(cb + q * 32 + b);
            off++;
            ww &= ww - 1;
        }
    }
    if (M > CAPW) M = CAPW;                    // never hit in practice
    __syncthreads();                           // all warps done reading bitmap
    if (tid < 32)                              // leave bitmap clean for next run
        ((uint4*)(g_bits + row * NW))[tid] = make_uint4(0u, 0u, 0u, 0u);

    // --- Phase B: warp `wid` = batch `wid` ---
    float*  tw  = tile[wid];
    float4* tw4 = (float4*)tw;
    const float* twl = tw + lane;              // immediate-offset base
    const float4* se4 = (const float4*)s_e[wid];
    const int kn   = lane >> 1;                // neighbor slot 0..15
    const int half = lane & 1;                 // which 16 features of the dot
    const int krow = lane >> 3;                // staging row group 0..3
    const int d4   = lane & 7;                 // staging f4 index 0..7

    float m = -INFINITY, ssum = 0.f;
    float acc0 = 0.f, acc1 = 0.f;

    // prologue: prefetch tile 0 into registers (clamped tail rows)
    float4 pre0, pre1, pre2, pre3;
    {
        const bool inr0 = (kn < ((M < TROWS) ? M : TROWS));
        const int  j0   = nbr[wid][inr0 ? kn : 0];
        pre0 = zb4[__shfl_sync(0xffffffffu, j0, 2 * (krow +  0)) * 8 + d4];
        pre1 = zb4[__shfl_sync(0xffffffffu, j0, 2 * (krow +  4)) * 8 + d4];
        pre2 = zb4[__shfl_sync(0xffffffffu, j0, 2 * (krow +  8)) * 8 + d4];
        pre3 = zb4[__shfl_sync(0xffffffffu, j0, 2 * (krow + 12)) * 8 + d4];
    }

    for (int t = 0; t < M; t += TROWS) {
        const int  rem = (M - t < TROWS) ? (M - t) : TROWS;   // warp-uniform
        const bool inr = (kn < rem);

        // store the prefetched tile
        tw4[(krow +  0) * 9 + d4] = pre0;
        tw4[(krow +  4) * 9 + d4] = pre1;
        tw4[(krow +  8) * 9 + d4] = pre2;
        tw4[(krow + 12) * 9 + d4] = pre3;
        __syncwarp();

        // issue next tile's gathers NOW (latency overlaps compute below)
        if (t + TROWS < M) {
            const int  r2   = M - t - TROWS;
            const bool inr2 = (kn < ((r2 < TROWS) ? r2 : TROWS));
            const int  j2   = nbr[wid][t + TROWS + (inr2 ? kn : 0)];
            pre0 = zb4[__shfl_sync(0xffffffffu, j2, 2 * (krow +  0)) * 8 + d4];
            pre1 = zb4[__shfl_sync(0xffffffffu, j2, 2 * (krow +  4)) * 8 + d4];
            pre2 = zb4[__shfl_sync(0xffffffffu, j2, 2 * (krow +  8)) * 8 + d4];
            pre3 = zb4[__shfl_sync(0xffffffffu, j2, 2 * (krow + 12)) * 8 + d4];
        }

        // half-dot: lane (2k+half) covers features [16*half, 16*half+16)
        float dd0 = 0.f, dd1 = 0.f;
#pragma unroll
        for (int i = 0; i < 4; i++) {
            const float4 vv = tw4[kn * 9 + half * 4 + i];
            const int f = half * 16 + 4 * i;
            dd0 = fmaf(vv.x, s_zi[wid][f + 0], dd0);
            dd1 = fmaf(vv.y, s_zi[wid][f + 1], dd1);
            dd0 = fmaf(vv.z, s_zi[wid][f + 2], dd0);
            dd1 = fmaf(vv.w, s_zi[wid][f + 3], dd1);
        }
        float p = dd0 + dd1;
        p += __shfl_xor_sync(0xffffffffu, p, 1);              // combine halves
        const float s = (p >= 0.f) ? p : 0.1f * p;            // LeakyReLU(0.1)
        const bool  valid = inr && (s != 0.f);                // att==0 -> masked
        const float sv = valid ? s : -INFINITY;

        const float tm = ord2f(__reduce_max_sync(0xffffffffu, f2ord(sv)));
        const float nm = fmaxf(m, tm);

        if (nm > -INFINITY) {                                 // warp-uniform
            const float e = valid ? __expf(sv - nm) : 0.f;
            if (half == 0) s_e[wid][kn] = e;                  // e=0 on tail rows
            if (m > -INFINITY) {                              // skip first tile
                const float corr = __expf(m - nm);
                acc0 *= corr;  acc1 *= corr;  ssum *= corr;
            }
            __syncwarp();
            // fully unrolled aggregation: immediate smem offsets, no tail
            const float4 e0 = se4[0], e1 = se4[1];
            const float4 e2 = se4[2], e3 = se4[3];
            acc0 = fmaf(e0.x, twl[ 0 * TPAD], acc0);
            acc1 = fmaf(e0.y, twl[ 1 * TPAD], acc1);
            acc0 = fmaf(e0.z, twl[ 2 * TPAD], acc0);
            acc1 = fmaf(e0.w, twl[ 3 * TPAD], acc1);
            acc0 = fmaf(e1.x, twl[ 4 * TPAD], acc0);
            acc1 = fmaf(e1.y, twl[ 5 * TPAD], acc1);
            acc0 = fmaf(e1.z, twl[ 6 * TPAD], acc0);
            acc1 = fmaf(e1.w, twl[ 7 * TPAD], acc1);
            acc0 = fmaf(e2.x, twl[ 8 * TPAD], acc0);
            acc1 = fmaf(e2.y, twl[ 9 * TPAD], acc1);
            acc0 = fmaf(e2.z, twl[10 * TPAD], acc0);
            acc1 = fmaf(e2.w, twl[11 * TPAD], acc1);
            acc0 = fmaf(e3.x, twl[12 * TPAD], acc0);
            acc1 = fmaf(e3.y, twl[13 * TPAD], acc1);
            acc0 = fmaf(e3.z, twl[14 * TPAD], acc0);
            acc1 = fmaf(e3.w, twl[15 * TPAD], acc1);
            const float t0 = (e0.x + e0.y) + (e0.z + e0.w);
            const float t1 = (e1.x + e1.y) + (e1.z + e1.w);
            const float t2 = (e2.x + e2.y) + (e2.z + e2.w);
            const float t3 = (e3.x + e3.y) + (e3.z + e3.w);
            ssum += (t0 + t1) + (t2 + t3);
            m = nm;
        }
        __syncwarp();
    }

    float o;
    if (m > -INFINITY) {
        o = (acc0 + acc1) / ssum;
    } else {
        // fully-masked row: softmax uniform over ALL 4096 columns
        float s2 = 0.f;
        for (int n = 0; n < NODES; n++) s2 += zb[n * OUTD + lane];
        o = s2 * (1.f / (float)NODES);
    }
    out[(wid * NODES + row) * OUTD + lane] = o;
}

// ---------------------------------------------------------------------------
extern "C" void kernel_launch(void* const* d_in, const int* in_sizes, int n_in,
                              void* d_out, int out_size) {
    const float* h       = (const float*)d_in[0];
    const float* W       = (const float*)d_in[1];
    const int*   adj_row = (const int*)d_in[2];
    const int*   adj_col = (const int*)d_in[3];
    float*       out     = (float*)d_out;

    k_z_set<<<(BC * NODES) / 16, 256>>>(h, W, adj_row, adj_col);
    k_gat  <<<NODES, 128>>>(out);
}

// round 14
// speedup vs baseline: 1.4623x; 1.0743x over previous
#include <cuda_runtime.h>
#include <math.h>

#define BC     4
#define NODES  4096
#define FEAT   64
#define OUTD   32
#define NEDGES (32 * NODES)
#define NW     (NODES / 32)   // 128 bitmap words per row
#define CAPW   128            // per-warp neighbor capacity (deg ~ Poisson(32))

// Scratch (no allocations in kernel_launch). g_bits is zero at module load;
// k_gat re-zeroes every word it consumes, so the bitmap is always clear when
// k_z_set's atomicOr scatter runs on the next call/replay.
__device__ float    g_z[BC * NODES * OUTD];   // 2 MB: z = h @ W
__device__ unsigned g_bits[NODES * NW];       // 2 MB: dedup'd adjacency bitmap

// ---------------------------------------------------------------------------
// Fused: z = h @ W (4 rows/warp -> 4 independent FMA chains; h warp-uniform
// float4, W staged in smem once per block) + edge scatter (1 edge/thread).
// 128-thread blocks, grid = 1024.
__global__ __launch_bounds__(128) void k_z_set(const float* __restrict__ h,
                                               const float* __restrict__ W,
                                               const int* __restrict__ erow,
                                               const int* __restrict__ ecol) {
    __shared__ __align__(16) float Ws[FEAT * OUTD];       // 8 KB
    const int tid = threadIdx.x;
#pragma unroll
    for (int i = 0; i < 4; i++)                            // 128*4 f4 = 8 KB
        ((float4*)Ws)[tid + 128 * i] = ((const float4*)W)[tid + 128 * i];

    const int gid = blockIdx.x * 128 + tid;                // exactly NEDGES
    {
        const int r = erow[gid], c = ecol[gid];
        atomicOr(&g_bits[r * NW + (c >> 5)], 1u << (c & 31));
    }
    __syncthreads();

    const int lane = tid & 31, wid = tid >> 5;
    const int r0 = (blockIdx.x * 4 + wid) * 4;             // 4 consecutive rows
    const float4* h4 = (const float4*)(h + (long)r0 * FEAT);
    float a0 = 0.f, a1 = 0.f, a2 = 0.f, a3 = 0.f;
#pragma unroll
    for (int q = 0; q < 16; q++) {
        const float4 h0 = h4[q];
        const float4 h1 = h4[16 + q];
        const float4 h2 = h4[32 + q];
        const float4 h3 = h4[48 + q];
        const float w0 = Ws[(4 * q + 0) * OUTD + lane];
        const float w1 = Ws[(4 * q + 1) * OUTD + lane];
        const float w2 = Ws[(4 * q + 2) * OUTD + lane];
        const float w3 = Ws[(4 * q + 3) * OUTD + lane];
        a0 = fmaf(h0.x, w0, a0); a0 = fmaf(h0.y, w1, a0);
        a0 = fmaf(h0.z, w2, a0); a0 = fmaf(h0.w, w3, a0);
        a1 = fmaf(h1.x, w0, a1); a1 = fmaf(h1.y, w1, a1);
        a1 = fmaf(h1.z, w2, a1); a1 = fmaf(h1.w, w3, a1);
        a2 = fmaf(h2.x, w0, a2); a2 = fmaf(h2.y, w1, a2);
        a2 = fmaf(h2.z, w2, a2); a2 = fmaf(h2.w, w3, a2);
        a3 = fmaf(h3.x, w0, a3); a3 = fmaf(h3.y, w1, a3);
        a3 = fmaf(h3.z, w2, a3); a3 = fmaf(h3.w, w3, a3);
    }
    g_z[(r0 + 0) * OUTD + lane] = a0;
    g_z[(r0 + 1) * OUTD + lane] = a1;
    g_z[(r0 + 2) * OUTD + lane] = a2;
    g_z[(r0 + 3) * OUTD + lane] = a3;
}

// ---------------------------------------------------------------------------
// Order-preserving float<->uint transform for __reduce_max_sync.
__device__ __forceinline__ unsigned f2ord(float f) {
    unsigned u = __float_as_uint(f);
    return (u & 0x80000000u) ? ~u : (u | 0x80000000u);
}
__device__ __forceinline__ float ord2f(unsigned u) {
    return __uint_as_float((u & 0x80000000u) ? (u & 0x7fffffffu) : ~u);
}

// One block per destination row; warp w owns batch w end-to-end.
// 16-row tiles; SOFTWARE-PIPELINED gather (R13, best measured k_gat).
#define TROWS 16
#define TPAD  36
__global__ __launch_bounds__(128, 9) void k_gat(float* __restrict__ out) {
    __shared__ unsigned short nbr[4][CAPW];
    __shared__ __align__(16) float tile[4][TROWS * TPAD];
    __shared__ __align__(16) float s_zi[4][32];
    __shared__ __align__(16) float s_e[4][TROWS];

    const int row  = blockIdx.x;
    const int tid  = threadIdx.x;
    const int lane = tid & 31, wid = tid >> 5;

    const float*  zb  = g_z + wid * NODES * OUTD;
    const float4* zb4 = (const float4*)zb;

    // two overlapping prefetches: z_i and this lane's 4 bitmap words
    const float zi = zb[row * OUTD + lane];
    const uint4 wv = ((const uint4*)(g_bits + row * NW))[lane];
    s_zi[wid][lane] = zi;

    // --- Phase A (per-warp): count, scan, extract ---
    const int cnt = __popc(wv.x) + __popc(wv.y) + __popc(wv.z) + __popc(wv.w);
    int v = cnt;
#pragma unroll
    for (int o = 1; o < 32; o <<= 1) {
        int t = __shfl_up_sync(0xffffffffu, v, o);
        if (lane >= o) v += t;
    }
    int M = __shfl_sync(0xffffffffu, v, 31);
    int off = v - cnt;
    const int cb = lane * 128;
    unsigned ws[4] = {wv.x, wv.y, wv.z, wv.w};
#pragma unroll
    for (int q = 0; q < 4; q++) {
        unsigned ww = ws[q];
        while (ww) {
            int b = __ffs(ww) - 1;
            if (off < CAPW) nbr[wid][off] = (unsigned short)(cb + q * 32 + b);
            off++;
            ww &= ww - 1;
        }
    }
    if (M > CAPW) M = CAPW;                    // never hit in practice
    __syncthreads();                           // all warps done reading bitmap
    if (tid < 32)                              // leave bitmap clean for next run
        ((uint4*)(g_bits + row * NW))[tid] = make_uint4(0u, 0u, 0u, 0u);

    // --- Phase B: warp `wid` = batch `wid` ---
    float*  tw  = tile[wid];
    float4* tw4 = (float4*)tw;
    const float* twl = tw + lane;              // immediate-offset base
    const float4* se4 = (const float4*)s_e[wid];
    const int kn   = lane >> 1;                // neighbor slot 0..15
    const int half = lane & 1;                 // which 16 features of the dot
    const int krow = lane >> 3;                // staging row group 0..3
    const int d4   = lane & 7;                 // staging f4 index 0..7

    float m = -INFINITY, ssum = 0.f;
    float acc0 = 0.f, acc1 = 0.f;

    // prologue: prefetch tile 0 into registers (clamped tail rows)
    float4 pre0, pre1, pre2, pre3;
    {
        const bool inr0 = (kn < ((M < TROWS) ? M : TROWS));
        const int  j0   = nbr[wid][inr0 ? kn : 0];
        pre0 = zb4[__shfl_sync(0xffffffffu, j0, 2 * (krow +  0)) * 8 + d4];
        pre1 = zb4[__shfl_sync(0xffffffffu, j0, 2 * (krow +  4)) * 8 + d4];
        pre2 = zb4[__shfl_sync(0xffffffffu, j0, 2 * (krow +  8)) * 8 + d4];
        pre3 = zb4[__shfl_sync(0xffffffffu, j0, 2 * (krow + 12)) * 8 + d4];
    }

    for (int t = 0; t < M; t += TROWS) {
        const bool inr = (t + kn < M);

        // store the prefetched tile
        tw4[(krow +  0) * 9 + d4] = pre0;
        tw4[(krow +  4) * 9 + d4] = pre1;
        tw4[(krow +  8) * 9 + d4] = pre2;
        tw4[(krow + 12) * 9 + d4] = pre3;
        __syncwarp();

        // issue next tile's gathers NOW (latency overlaps compute below)
        if (t + TROWS < M) {
            const bool inr2 = (t + TROWS + kn < M);
            const int  j2   = nbr[wid][t + TROWS + (inr2 ? kn : 0)];
            pre0 = zb4[__shfl_sync(0xffffffffu, j2, 2 * (krow +  0)) * 8 + d4];
            pre1 = zb4[__shfl_sync(0xffffffffu, j2, 2 * (krow +  4)) * 8 + d4];
            pre2 = zb4[__shfl_sync(0xffffffffu, j2, 2 * (krow +  8)) * 8 + d4];
            pre3 = zb4[__shfl_sync(0xffffffffu, j2, 2 * (krow + 12)) * 8 + d4];
        }

        // half-dot: lane (2k+half) covers features [16*half, 16*half+16)
        float dd0 = 0.f, dd1 = 0.f;
#pragma unroll
        for (int i = 0; i < 4; i++) {
            const float4 vv = tw4[kn * 9 + half * 4 + i];
            const int f = half * 16 + 4 * i;
            dd0 = fmaf(vv.x, s_zi[wid][f + 0], dd0);
            dd1 = fmaf(vv.y, s_zi[wid][f + 1], dd1);
            dd0 = fmaf(vv.z, s_zi[wid][f + 2], dd0);
            dd1 = fmaf(vv.w, s_zi[wid][f + 3], dd1);
        }
        float p = dd0 + dd1;
        p += __shfl_xor_sync(0xffffffffu, p, 1);              // combine halves
        const float s = (p >= 0.f) ? p : 0.1f * p;            // LeakyReLU(0.1)
        const bool  valid = inr && (s != 0.f);                // att==0 -> masked
        const float sv = valid ? s : -INFINITY;

        const float tm = ord2f(__reduce_max_sync(0xffffffffu, f2ord(sv)));
        const float nm = fmaxf(m, tm);

        if (nm > -INFINITY) {                                 // warp-uniform
            const float e = valid ? __expf(sv - nm) : 0.f;
            if (half == 0) s_e[wid][kn] = e;                  // e=0 on tail rows
            if (m > -INFINITY) {                              // skip first tile
                const float corr = __expf(m - nm);
                acc0 *= corr;  acc1 *= corr;  ssum *= corr;
            }
            __syncwarp();
            // fully unrolled aggregation: immediate smem offsets, no tail
            const float4 e0 = se4[0], e1 = se4[1];
            const float4 e2 = se4[2], e3 = se4[3];
            acc0 = fmaf(e0.x, twl[ 0 * TPAD], acc0);
            acc1 = fmaf(e0.y, twl[ 1 * TPAD], acc1);
            acc0 = fmaf(e0.z, twl[ 2 * TPAD], acc0);
            acc1 = fmaf(e0.w, twl[ 3 * TPAD], acc1);
            acc0 = fmaf(e1.x, twl[ 4 * TPAD], acc0);
            acc1 = fmaf(e1.y, twl[ 5 * TPAD], acc1);
            acc0 = fmaf(e1.z, twl[ 6 * TPAD], acc0);
            acc1 = fmaf(e1.w, twl[ 7 * TPAD], acc1);
            acc0 = fmaf(e2.x, twl[ 8 * TPAD], acc0);
            acc1 = fmaf(e2.y, twl[ 9 * TPAD], acc1);
            acc0 = fmaf(e2.z, twl[10 * TPAD], acc0);
            acc1 = fmaf(e2.w, twl[11 * TPAD], acc1);
            acc0 = fmaf(e3.x, twl[12 * TPAD], acc0);
            acc1 = fmaf(e3.y, twl[13 * TPAD], acc1);
            acc0 = fmaf(e3.z, twl[14 * TPAD], acc0);
            acc1 = fmaf(e3.w, twl[15 * TPAD], acc1);
            const float t0 = (e0.x + e0.y) + (e0.z + e0.w);
            const float t1 = (e1.x + e1.y) + (e1.z + e1.w);
            const float t2 = (e2.x + e2.y) + (e2.z + e2.w);
            const float t3 = (e3.x + e3.y) + (e3.z + e3.w);
            ssum += (t0 + t1) + (t2 + t3);
            m = nm;
        }
        __syncwarp();
    }

    float o;
    if (m > -INFINITY) {
        o = (acc0 + acc1) / ssum;
    } else {
        // fully-masked row: softmax uniform over ALL 4096 columns
        float s2 = 0.f;
        for (int n = 0; n < NODES; n++) s2 += zb[n * OUTD + lane];
        o = s2 * (1.f / (float)NODES);
    }
    out[(wid * NODES + row) * OUTD + lane] = o;
}

// ---------------------------------------------------------------------------
extern "C" void kernel_launch(void* const* d_in, const int* in_sizes, int n_in,
                              void* d_out, int out_size) {
    const float* h       = (const float*)d_in[0];
    const float* W       = (const float*)d_in[1];
    const int*   adj_row = (const int*)d_in[2];
    const int*   adj_col = (const int*)d_in[3];
    float*       out     = (float*)d_out;

    k_z_set<<<NEDGES / 128, 128>>>(h, W, adj_row, adj_col);
    k_gat  <<<NODES, 128>>>(out);
}